// round 10
// baseline (speedup 1.0000x reference)
#include <cuda_runtime.h>
#include <cuda_fp16.h>
#include <cstdint>

// Problem constants (fixed by the reference setup_inputs).
constexpr int B  = 4096;   // batch rows
constexpr int D  = 784;    // feature dim
constexpr int O1 = 8192;   // pair terms
constexpr int O2 = 8192;   // triple terms
constexpr int OT = O1 + O2;
constexpr int R  = 8;      // rows per block (packed as 8x fp16 in uint4)
constexpr int REP = 8;     // copies: one per 16B group of a 128B line -> 4-phase LDS.128
constexpr int NTHREADS = 512;
constexpr int SMEM_BYTES = D * REP * (int)sizeof(uint4);  // 100352 B

__device__ __forceinline__ __half2 u2h2(unsigned u) {
    return *reinterpret_cast<const __half2*>(&u);
}
__device__ __forceinline__ unsigned hmul2u(unsigned a, unsigned b) {
    const __half2 t = __hmul2(u2h2(a), u2h2(b));
    return *reinterpret_cast<const unsigned*>(&t);
}
__device__ __forceinline__ unsigned hmul3u(unsigned a, unsigned b, unsigned c) {
    const __half2 t = __hmul2(__hmul2(u2h2(a), u2h2(b)), u2h2(c));
    return *reinterpret_cast<const unsigned*>(&t);
}

// q[o] holds rows (2rp, 2rp+1) of output o as half2 (for one rp).
// Emit the two row-float4s {P(o0..o3, row)} and store them (streaming).
__device__ __forceinline__ void store_rp(float* outp, size_t OTs, int rp, int o0,
                                         unsigned q0, unsigned q1,
                                         unsigned q2, unsigned q3) {
    const unsigned lo01 = __byte_perm(q0, q1, 0x5410);
    const unsigned lo23 = __byte_perm(q2, q3, 0x5410);
    const unsigned hi01 = __byte_perm(q0, q1, 0x7632);
    const unsigned hi23 = __byte_perm(q2, q3, 0x7632);
    const float2 a = __half22float2(u2h2(lo01));
    const float2 b = __half22float2(u2h2(lo23));
    const float2 c = __half22float2(u2h2(hi01));
    const float2 d = __half22float2(u2h2(hi23));
    __stcs(reinterpret_cast<float4*>(outp + (size_t)(2 * rp + 0) * OTs + o0),
           make_float4(a.x, a.y, b.x, b.y));
    __stcs(reinterpret_cast<float4*>(outp + (size_t)(2 * rp + 1) * OTs + o0),
           make_float4(c.x, c.y, d.x, d.y));
}

__global__ __launch_bounds__(NTHREADS, 2)
void random_de_kernel(const float* __restrict__ x,
                      const int*   __restrict__ idx1,
                      const int*   __restrict__ idx2,
                      float*       __restrict__ out)
{
    // xs[d*8 + k] = half8{x[row0..row0+7][d]}, identical for k = 0..7.
    // Byte addr (d*8+k)*16 mod 128 == 16k -> 16B group fixed by k, independent
    // of d: with k = lane&7 every gather LDS.128 is the 4-phase minimum.
    extern __shared__ uint4 xs[];

    const int row0 = blockIdx.x * R;
    const int part = blockIdx.y;          // 0: pairs, 1: triples
    const int tid  = threadIdx.x;

    // ---- Stage: 8 rows -> raw fp16 octets, 8 bank-slot copies ----
    {
        const float* xr[R];
        #pragma unroll
        for (int r = 0; r < R; r++) xr[r] = x + (size_t)(row0 + r) * D;
        #pragma unroll 2
        for (int i = tid; i < D * REP; i += NTHREADS) {
            const int d = i >> 3;         // 8 consecutive lanes share d (broadcast loads)
            const __half2 h0 = __floats2half2_rn(__ldg(xr[0] + d), __ldg(xr[1] + d));
            const __half2 h1 = __floats2half2_rn(__ldg(xr[2] + d), __ldg(xr[3] + d));
            const __half2 h2 = __floats2half2_rn(__ldg(xr[4] + d), __ldg(xr[5] + d));
            const __half2 h3 = __floats2half2_rn(__ldg(xr[6] + d), __ldg(xr[7] + d));
            uint4 v;
            v.x = *reinterpret_cast<const unsigned*>(&h0);
            v.y = *reinterpret_cast<const unsigned*>(&h1);
            v.z = *reinterpret_cast<const unsigned*>(&h2);
            v.w = *reinterpret_cast<const unsigned*>(&h3);
            xs[i] = v;   // consecutive i across lanes -> conflict-free STS.128
        }
    }
    __syncthreads();

    const int k = tid & 7;                      // this lane's copy slot
    const uint4* __restrict__ xk = xs + k;      // access: xk[idx * 8]

    if (part == 0) {
        // ---- Pairs: outputs [0, O1), 4 outputs per thread-iter ----
        const int4* __restrict__ idx1v = reinterpret_cast<const int4*>(idx1);
        float* outp = out + (size_t)row0 * OT;
        #pragma unroll
        for (int g = tid; g < O1 / 4; g += NTHREADS) {
            const int o0 = g * 4;
            const int4 p0 = __ldg(&idx1v[g * 2 + 0]);   // {a0,b0,a1,b1}
            const int4 p1 = __ldg(&idx1v[g * 2 + 1]);   // {a2,b2,a3,b3}
            // 8 independent gathers in flight
            const uint4 A0 = xk[p0.x * 8];
            const uint4 B0 = xk[p0.y * 8];
            const uint4 A1 = xk[p0.z * 8];
            const uint4 B1 = xk[p0.w * 8];
            const uint4 A2 = xk[p1.x * 8];
            const uint4 B2 = xk[p1.y * 8];
            const uint4 A3 = xk[p1.z * 8];
            const uint4 B3 = xk[p1.w * 8];
            unsigned q0[4], q1[4], q2[4], q3[4];
            q0[0] = hmul2u(A0.x, B0.x); q0[1] = hmul2u(A0.y, B0.y);
            q0[2] = hmul2u(A0.z, B0.z); q0[3] = hmul2u(A0.w, B0.w);
            q1[0] = hmul2u(A1.x, B1.x); q1[1] = hmul2u(A1.y, B1.y);
            q1[2] = hmul2u(A1.z, B1.z); q1[3] = hmul2u(A1.w, B1.w);
            q2[0] = hmul2u(A2.x, B2.x); q2[1] = hmul2u(A2.y, B2.y);
            q2[2] = hmul2u(A2.z, B2.z); q2[3] = hmul2u(A2.w, B2.w);
            q3[0] = hmul2u(A3.x, B3.x); q3[1] = hmul2u(A3.y, B3.y);
            q3[2] = hmul2u(A3.z, B3.z); q3[3] = hmul2u(A3.w, B3.w);
            #pragma unroll
            for (int rp = 0; rp < 4; rp++)
                store_rp(outp, OT, rp, o0, q0[rp], q1[rp], q2[rp], q3[rp]);
        }
    } else {
        // ---- Triples: outputs [O1, OT), 4 outputs per thread-iter ----
        const int4* __restrict__ idx2v = reinterpret_cast<const int4*>(idx2);
        float* outp = out + (size_t)row0 * OT + O1;
        #pragma unroll
        for (int g = tid; g < O2 / 4; g += NTHREADS) {
            const int o0 = g * 4;
            const int4 t0 = __ldg(&idx2v[g * 3 + 0]);   // {a0,b0,c0,a1}
            const int4 t1 = __ldg(&idx2v[g * 3 + 1]);   // {b1,c1,a2,b2}
            const int4 t2 = __ldg(&idx2v[g * 3 + 2]);   // {c2,a3,b3,c3}
            unsigned q0[4], q1[4], q2[4], q3[4];
            // First half: outputs 0,1 (6 gathers live)
            {
                const uint4 A0 = xk[t0.x * 8];
                const uint4 B0 = xk[t0.y * 8];
                const uint4 C0 = xk[t0.z * 8];
                const uint4 A1 = xk[t0.w * 8];
                const uint4 B1 = xk[t1.x * 8];
                const uint4 C1 = xk[t1.y * 8];
                q0[0] = hmul3u(A0.x, B0.x, C0.x); q0[1] = hmul3u(A0.y, B0.y, C0.y);
                q0[2] = hmul3u(A0.z, B0.z, C0.z); q0[3] = hmul3u(A0.w, B0.w, C0.w);
                q1[0] = hmul3u(A1.x, B1.x, C1.x); q1[1] = hmul3u(A1.y, B1.y, C1.y);
                q1[2] = hmul3u(A1.z, B1.z, C1.z); q1[3] = hmul3u(A1.w, B1.w, C1.w);
            }
            // Second half: outputs 2,3
            {
                const uint4 A2 = xk[t1.z * 8];
                const uint4 B2 = xk[t1.w * 8];
                const uint4 C2 = xk[t2.x * 8];
                const uint4 A3 = xk[t2.y * 8];
                const uint4 B3 = xk[t2.z * 8];
                const uint4 C3 = xk[t2.w * 8];
                q2[0] = hmul3u(A2.x, B2.x, C2.x); q2[1] = hmul3u(A2.y, B2.y, C2.y);
                q2[2] = hmul3u(A2.z, B2.z, C2.z); q2[3] = hmul3u(A2.w, B2.w, C2.w);
                q3[0] = hmul3u(A3.x, B3.x, C3.x); q3[1] = hmul3u(A3.y, B3.y, C3.y);
                q3[2] = hmul3u(A3.z, B3.z, C3.z); q3[3] = hmul3u(A3.w, B3.w, C3.w);
            }
            #pragma unroll
            for (int rp = 0; rp < 4; rp++)
                store_rp(outp, OT, rp, o0, q0[rp], q1[rp], q2[rp], q3[rp]);
        }
    }
}

extern "C" void kernel_launch(void* const* d_in, const int* in_sizes, int n_in,
                              void* d_out, int out_size)
{
    const float* x    = (const float*)d_in[0];
    const int*   idx1 = (const int*)d_in[1];
    const int*   idx2 = (const int*)d_in[2];
    float*       out  = (float*)d_out;

    // Non-stream API: executes immediately, capture-safe, idempotent.
    cudaFuncSetAttribute(random_de_kernel,
                         cudaFuncAttributeMaxDynamicSharedMemorySize,
                         SMEM_BYTES);

    dim3 grid(B / R, 2);   // 512 row-octets x {pairs, triples} = 1024 blocks
    random_de_kernel<<<grid, NTHREADS, SMEM_BYTES>>>(x, idx1, idx2, out);
}